// round 16
// baseline (speedup 1.0000x reference)
#include <cuda_runtime.h>
#include <math.h>
#include <stdint.h>

#define Bn 4
#define Sn 512
#define Hd 128
#define En 32     // embed_dim — E=32 (V,E,H = 128,32,128)
#define Vv 128
#define G4 512    // 4*H
#define CL 4      // cluster size for LSTM

typedef unsigned long long u64;

// ---------------- scratch (device globals: no allocation allowed) ----------------
__device__ float g_xproj[Bn*Sn*G4];   // 4 MB
__device__ float g_out[Bn*Sn*Hd];     // 1 MB
__device__ float g_q[Bn*Sn*Hd];       // 1 MB
__device__ float g_k[Bn*Sn*Hd];       // 1 MB
__device__ float g_scores[Bn*Sn*Sn];  // 4 MB (raw scores; softmax fused downstream)
__device__ float g_state_dump[2*Bn*Hd];

// ---------------- helpers ----------------
__device__ __forceinline__ u64 fma2(u64 a, u64 b, u64 c) {
    u64 d;
    asm("fma.rn.f32x2 %0, %1, %2, %3;" : "=l"(d) : "l"(a), "l"(b), "l"(c));
    return d;
}
__device__ __forceinline__ u64 add2(u64 a, u64 b) {
    u64 d;
    asm("add.rn.f32x2 %0, %1, %2;" : "=l"(d) : "l"(a), "l"(b));
    return d;
}
__device__ __forceinline__ float sig_f(float x) {
    return __fdividef(1.0f, 1.0f + __expf(-x));
}
__device__ __forceinline__ float tanh_f(float x) {
    float e = __expf(-2.0f * x);
    return __fdividef(1.0f - e, 1.0f + e);
}
__device__ __forceinline__ float tanh_a(float x) {
    float y;
    asm("tanh.approx.f32 %0, %1;" : "=f"(y) : "f"(x));
    return y;
}
__device__ __forceinline__ uint32_t smem_u32(const void* p) {
    uint32_t a;
    asm("{ .reg .u64 t; cvta.to.shared.u64 t, %1; cvt.u32.u64 %0, t; }"
        : "=r"(a) : "l"(p));
    return a;
}
__device__ __forceinline__ uint32_t mapa_peer(uint32_t local_addr, uint32_t peer_rank) {
    uint32_t r;
    asm("mapa.shared::cluster.u32 %0, %1, %2;" : "=r"(r) : "r"(local_addr), "r"(peer_rank));
    return r;
}
__device__ __forceinline__ void mbar_init(uint32_t mbar, uint32_t count) {
    asm volatile("mbarrier.init.shared.b64 [%0], %1;" :: "r"(mbar), "r"(count) : "memory");
}
__device__ __forceinline__ void mbar_expect_tx(uint32_t mbar, uint32_t bytes) {
    asm volatile("mbarrier.arrive.expect_tx.shared.b64 _, [%0], %1;"
                 :: "r"(mbar), "r"(bytes) : "memory");
}
__device__ __forceinline__ void st_async_b32(uint32_t dst, float v, uint32_t mbar) {
    asm volatile(
        "st.async.shared::cluster.mbarrier::complete_tx::bytes.b32 [%0], %1, [%2];"
        :: "r"(dst), "r"(__float_as_uint(v)), "r"(mbar) : "memory");
}
__device__ __forceinline__ void mbar_wait_cta(uint32_t mbar, uint32_t parity) {
    uint32_t done;
    asm volatile(
        "{\n\t"
        ".reg .pred p;\n\t"
        "mbarrier.try_wait.parity.acquire.cta.shared::cta.b64 p, [%1], %2;\n\t"
        "selp.b32 %0, 1, 0, p;\n\t"
        "}"
        : "=r"(done) : "r"(mbar), "r"(parity) : "memory");
    if (!done) {
        asm volatile(
            "{\n\t"
            ".reg .pred P;\n\t"
            "WAIT_LOOP_%=:\n\t"
            "mbarrier.try_wait.parity.acquire.cta.shared::cta.b64 P, [%0], %1, 0x989680;\n\t"
            "@P bra.uni WAIT_DONE_%=;\n\t"
            "bra.uni WAIT_LOOP_%=;\n\t"
            "WAIT_DONE_%=:\n\t"
            "}"
            :: "r"(mbar), "r"(parity) : "memory");
    }
}

// ============================================================================
// Kernel 1: xproj[r, col] = dot(emb[x[r], :32], W_ih[col, :32]) + b_ih + b_hh
// ============================================================================
__global__ void k_embed_xproj(const int* __restrict__ x, const float* __restrict__ emb,
                              const float* __restrict__ Wih, const float* __restrict__ bih,
                              const float* __restrict__ bhh) {
    __shared__ __align__(16) float e_s[16 * En];
    int tid = threadIdx.x;                          // 512
    int r0 = blockIdx.x * 16;
    e_s[tid] = emb[x[r0 + (tid >> 5)] * En + (tid & 31)];
    __syncthreads();

    int col = tid;
    const float4* W4 = (const float4*)(Wih + col * En);
    float4 w[8];
#pragma unroll
    for (int i = 0; i < 8; i++) w[i] = W4[i];
    float bb = bih[col] + bhh[col];

#pragma unroll 4
    for (int r = 0; r < 16; r++) {
        const float4* e4 = (const float4*)(e_s + r * En);
        float a = bb;
#pragma unroll
        for (int i = 0; i < 8; i++) {
            float4 e = e4[i];
            a = fmaf(w[i].x, e.x, a);
            a = fmaf(w[i].y, e.y, a);
            a = fmaf(w[i].z, e.z, a);
            a = fmaf(w[i].w, e.w, a);
        }
        g_xproj[(size_t)(r0 + r) * G4 + col] = a;
    }
}

// ============================================================================
// Kernel 2: LSTM — 4-CTA cluster per batch, PARTITIONED BY H-INDEX.
// CTA r owns h-indices [r*32, r*32+32) and computes ALL FOUR gates for them
// locally (128 rows/CTA: local row l -> gate l>>5, h_local l&31; global W_hh
// row = gate*128 + rank*32 + h_local). Gates are consumed locally (plain STS
// + __syncthreads — no DSMEM for gates). Phase B runs on warp 0 only (32 h's,
// no cross-CTA redundancy), then each lane st.asyncs its h to all 4 CTAs'
// hbuf[nbank] (128 floats = 512 B total per CTA, 4x less than gate exchange).
// Only warp 0 polls the h-mbarrier; __syncthreads releases the rest.
// hbuf/mbar double-banked; wait parity = (((t+1)>>1)&1)^1 (mbar[b] completes
// at steps b+1, b+3, ...); tid0 re-arms mbar[bank] right after the wait
// (arm precedes this CTA's mid-sync => precedes any CTA's next phase B).
// Dot math (half-split + shfl_xor(1)) unchanged -> bit-identical h.
// ============================================================================
__global__ void __cluster_dims__(CL, 1, 1) __launch_bounds__(256, 1)
k_lstm(const float* __restrict__ Whh, float* __restrict__ hT, float* __restrict__ cT) {
    __shared__ __align__(16) float hbuf[2][128];
    __shared__ __align__(16) float dots_s[128];
    __shared__ __align__(8)  u64  mbar[2];

    int tid = threadIdx.x;
    uint32_t rank;
    asm("mov.u32 %0, %%cluster_ctarank;" : "=r"(rank));
    int b = blockIdx.x / CL;
    int row_local = tid >> 1;             // 0..127
    int p         = tid & 1;              // half index
    int gate      = row_local >> 5;       // 0..3 (warp-uniform: warp w -> gate w>>1)
    int h_local   = row_local & 31;
    int row_global = gate * 128 + (int)rank * 32 + h_local;   // W_hh / xproj row
    bool is_g_gate = (gate == 2);

    // 64 weight floats (half row) -> 32 u64 register pairs
    const ulonglong2* wsrc = (const ulonglong2*)(Whh + (size_t)row_global * Hd + p * 64);
    u64 w[32];
#pragma unroll
    for (int q = 0; q < 16; q++) {
        ulonglong2 v = wsrc[q];
        w[2 * q]     = v.x;
        w[2 * q + 1] = v.y;
    }

    uint32_t mbar_a[2] = { smem_u32(&mbar[0]), smem_u32(&mbar[1]) };
    // phase-B store targets (meaningful for tid<32): h slot rank*32+lane in
    // every CTA's hbuf[nbank], completing on that CTA's mbar[nbank].
    int lane = tid & 31;
    uint32_t hsrc[2] = { smem_u32(&hbuf[0][(int)rank * 32 + lane]),
                         smem_u32(&hbuf[1][(int)rank * 32 + lane]) };
    uint32_t hdst[2][CL], hmr[2][CL];
#pragma unroll
    for (int d = 0; d < CL; d++) {
        hdst[0][d] = mapa_peer(hsrc[0], d);
        hdst[1][d] = mapa_peer(hsrc[1], d);
        hmr[0][d]  = mapa_peer(mbar_a[0], d);
        hmr[1][d]  = mapa_peer(mbar_a[1], d);
    }

    if (tid < 128) hbuf[0][tid] = 0.0f;   // h_{-1} = 0, read at t=0 (bank 0)
    if (tid == 0) {
        mbar_init(mbar_a[0], 1);
        mbar_init(mbar_a[1], 1);
        mbar_expect_tx(mbar_a[1], 512);   // arm for t=0 phase B (h for t=1)
    }
    float c = 0.0f, hlast = 0.0f, clast = 0.0f;

    // cluster barrier: init/arm/hbuf visible before any remote traffic
    asm volatile("barrier.cluster.arrive.aligned;" ::: "memory");
    asm volatile("barrier.cluster.wait.aligned;" ::: "memory");

    const float* xpb  = g_xproj + (size_t)b * Sn * G4;
    float*       outb = g_out   + (size_t)b * Sn * Hd;
    int hq = p * 16;                                   // this half's h range

    float xprow = xpb[row_global];                     // t = 0 (pipelined)

    for (int t = 0; t < Sn; t++) {
        uint32_t bank  = t & 1;
        uint32_t nbank = bank ^ 1;
        // warp 0 polls for this step's h (stores from all CTAs' t-1 phase B);
        // then tid0 re-arms mbar[bank] for its next completion cycle.
        if (tid < 32) {
            if (t > 0) {
                uint32_t par = (((uint32_t)(t + 1) >> 1) & 1u) ^ 1u;
                mbar_wait_cta(mbar_a[bank], par);
            }
            if (tid == 0)
                mbar_expect_tx(mbar_a[bank], 512);
        }
        __syncthreads();                           // release all warps: h ready

        float xprow_next = (t + 1 < Sn) ? xpb[(size_t)(t + 1) * G4 + row_global] : 0.0f;

        // phase A: half-row dot against hbuf[bank] (LDS.128 broadcast)
        const ulonglong2* h2v = (const ulonglong2*)hbuf[bank];
        u64 a0 = 0ull, a1 = 0ull, a2 = 0ull, a3 = 0ull;
#pragma unroll
        for (int q = 0; q < 16; q += 2) {
            ulonglong2 hv0 = h2v[hq + q];
            ulonglong2 hv1 = h2v[hq + q + 1];
            a0 = fma2(w[2 * q],     hv0.x, a0);
            a1 = fma2(w[2 * q + 1], hv0.y, a1);
            a2 = fma2(w[2 * q + 2], hv1.x, a2);
            a3 = fma2(w[2 * q + 3], hv1.y, a3);
        }
        u64 ssum = add2(add2(a0, a1), add2(a2, a3));
        float2 sf = *(float2*)&ssum;
        float mysum = sf.x + sf.y;
        mysum += __shfl_xor_sync(0xFFFFFFFFu, mysum, 1);
        if (p == 0) {
            float pre = xprow + mysum;
            dots_s[row_local] = is_g_gate ? tanh_f(pre) : sig_f(pre);  // local only
        }
        __syncthreads();                           // gates ready for phase B

        // phase B: warp 0 updates this CTA's 32 h's, broadcasts them
        if (tid < 32) {
            float ai = dots_s[tid];
            float af = dots_s[tid + 32];
            float ag = dots_s[tid + 64];
            float ao = dots_s[tid + 96];
            c = af * c + ai * ag;
            float h = ao * tanh_f(c);
            outb[(size_t)t * Hd + (int)rank * 32 + tid] = h;   // disjoint slices
            hlast = h;
            clast = c;
            if (t + 1 < Sn) {
#pragma unroll
                for (int d = 0; d < CL; d++)
                    st_async_b32(hdst[nbank][d], h, hmr[nbank][d]);
            }
        }
        xprow = xprow_next;
        // no trailing sync needed: next iteration's mbar-wait + __syncthreads
        // orders everything (producers can't overwrite dots_s until after it).
    }
    if (tid < 32) {
        hT[b * Hd + (int)rank * 32 + tid] = hlast;
        cT[b * Hd + (int)rank * 32 + tid] = clast;
    }
    // no CTA may exit while peer remote ops could be in flight
    asm volatile("barrier.cluster.arrive.aligned;" ::: "memory");
    asm volatile("barrier.cluster.wait.aligned;" ::: "memory");
}

// ============================================================================
// Kernel 3: q = out @ Wqᵀ + bq ; k = out @ Wkᵀ + bk. 16 rows/block, 256 thr.
// ============================================================================
__global__ void k_qk(const float* __restrict__ Wq, const float* __restrict__ bq,
                     const float* __restrict__ Wk, const float* __restrict__ bk) {
    __shared__ __align__(16) float o_s[16 * 128];
    int tid = threadIdx.x;
    int r0 = blockIdx.x * 16;
    for (int i = tid; i < 2048; i += 256)
        o_s[i] = g_out[(size_t)r0 * Hd + i];
    __syncthreads();

    const float* W    = (tid < 128) ? Wq : Wk;
    const float* bias = (tid < 128) ? bq : bk;
    float*       dst  = (tid < 128) ? g_q : g_k;
    int c = tid & 127;

    const float4* W4  = (const float4*)W;
    const float4* os4 = (const float4*)o_s;
    float acc[16];
    float bb = bias[c];
#pragma unroll
    for (int r = 0; r < 16; r++) acc[r] = bb;
#pragma unroll 4
    for (int k4 = 0; k4 < 32; k4++) {
        float4 w = W4[c * 32 + k4];
#pragma unroll
        for (int r = 0; r < 16; r++) {
            float4 o = os4[r * 32 + k4];
            acc[r] = fmaf(w.x, o.x, acc[r]);
            acc[r] = fmaf(w.y, o.y, acc[r]);
            acc[r] = fmaf(w.z, o.z, acc[r]);
            acc[r] = fmaf(w.w, o.w, acc[r]);
        }
    }
#pragma unroll
    for (int r = 0; r < 16; r++)
        dst[(size_t)(r0 + r) * Hd + c] = acc[r];
}

// ============================================================================
// Kernel 4: RAW scores via hardware tanh.approx. 32x32 causal tiles.
// ============================================================================
__global__ void k_scores(const float* __restrict__ v) {
    __shared__ __align__(16) float q_s[32 * 128];
    __shared__ float kT[128 * 33];
    __shared__ float v_s[128];
    int tid = threadIdx.x;
    int b = blockIdx.x / 136;
    int r = blockIdx.x % 136;
    int si = 0;
    while (((si + 1) * (si + 2)) >> 1 <= r) si++;
    int ti = r - ((si * (si + 1)) >> 1);
    int s0 = si * 32, t0 = ti * 32;

    const float* qb = g_q + ((size_t)b * Sn + s0) * Hd;
    const float* kb = g_k + ((size_t)b * Sn + t0) * Hd;
    for (int i = tid; i < 4096; i += 256) q_s[i] = qb[i];
    for (int i = tid; i < 4096; i += 256) {
        int tt = i >> 7, h = i & 127;
        kT[h * 33 + tt] = kb[i];
    }
    if (tid < 128) v_s[tid] = v[tid];
    __syncthreads();

    int tl = tid & 31, sb = tid >> 5;
    float acc[4] = {0.f, 0.f, 0.f, 0.f};
#pragma unroll 2
    for (int h = 0; h < 128; h++) {
        float kv = kT[h * 33 + tl];
        float vv = v_s[h];
#pragma unroll
        for (int p = 0; p < 4; p++)
            acc[p] = fmaf(vv, tanh_a(q_s[(sb + (p << 3)) * 128 + h] + kv), acc[p]);
    }
    int t = t0 + tl;
#pragma unroll
    for (int p = 0; p < 4; p++) {
        int s = s0 + sb + (p << 3);
        if (t <= s)
            g_scores[((size_t)b * Sn + s) * Sn + t] = acc[p];
    }
}

// ============================================================================
// Kernel 5: FUSED softmax + ctx + logits. 32 s-rows/block, 256 threads.
// ============================================================================
__global__ void k_ctx_logits(const float* __restrict__ Wf, const float* __restrict__ bf,
                             float* __restrict__ logits) {
    __shared__ float w_s[32 * 32];
    __shared__ __align__(16) float ctx_s[32 * 128];
    __shared__ __align__(16) float out_s[32 * 128];
    __shared__ float m_s[32], iz_s[32];
    int tid = threadIdx.x;
    int b  = blockIdx.x >> 4;
    int s0 = (blockIdx.x & 15) << 5;

    for (int i = tid; i < 4096; i += 256)
        out_s[i] = g_out[((size_t)b * Sn + s0) * Hd + i];

    // ---- pass 1: softmax stats (8 lanes per row) ----
    {
        int row = tid >> 3;
        int l8  = tid & 7;
        int s = s0 + row;
        int n = s + 1;
        const float* sc = g_scores + ((size_t)b * Sn + s) * Sn;
        float mx = -1e30f;
        for (int t = l8; t < n; t += 8)
            mx = fmaxf(mx, sc[t]);
#pragma unroll
        for (int o = 4; o > 0; o >>= 1)
            mx = fmaxf(mx, __shfl_xor_sync(0xFFFFFFFFu, mx, o));
        float sum = 0.0f;
        for (int t = l8; t < n; t += 8)
            sum += __expf(sc[t] - mx);
#pragma unroll
        for (int o = 4; o > 0; o >>= 1)
            sum += __shfl_xor_sync(0xFFFFFFFFu, sum, o);
        if (l8 == 0) {
            m_s[row]  = mx;
            iz_s[row] = __fdividef(1.0f, sum);
        }
    }
    __syncthreads();

    // ---- pass 2: ctx = softmax(scores) @ out ----
    int h = tid & 127, sg = tid >> 7;
    float acc[16];
#pragma unroll
    for (int i = 0; i < 16; i++) acc[i] = 0.0f;

    int tend = s0 + 32;
    for (int tc0 = 0; tc0 < tend; tc0 += 32) {
        __syncthreads();
        for (int i = tid; i < 1024; i += 256) {
            int sl = i >> 5, tc = i & 31;
            int s = s0 + sl;
            int t = tc0 + tc;
            float wv = 0.0f;
            if (t <= s)
                wv = __expf(g_scores[((size_t)b * Sn + s) * Sn + t] - m_s[sl]) * iz_s[sl];
            w_s[i] = wv;
        }
        __syncthreads();
#pragma unroll 4
        for (int tc = 0; tc < 32; tc++) {
            float ov = g_out[((size_t)b * Sn + tc0 + tc) * Hd + h];
#pragma unroll
            for (int i = 0; i < 16; i++)
                acc[i] = fmaf(w_s[(2 * i + sg) * 32 + tc], ov, acc[i]);
        }
    }
    __syncthreads();
#pragma unroll
    for (int i = 0; i < 16; i++) ctx_s[(2 * i + sg) * 128 + h] = acc[i];
    __syncthreads();

    // ---- logits tile ----
    int vc = tid & 127;
    float bb = bf[vc];
    const float4* Wf4 = (const float4*)Wf;
    const float4* os4 = (const float4*)out_s;
    const float4* cs4 = (const float4*)ctx_s;
    float acc2[16];
#pragma unroll
    for (int i = 0; i < 16; i++) acc2[i] = 0.0f;
#pragma unroll 2
    for (int k4 = 0; k4 < 32; k4++) {
        float4 w = Wf4[vc * 64 + k4];
#pragma unroll
        for (int i = 0; i < 16; i++) {
            float4 o = os4[(2 * i + sg) * 32 + k4];
            acc2[i] = fmaf(w.x, o.x, acc2[i]);
            acc2[i] = fmaf(w.y, o.y, acc2[i]);
            acc2[i] = fmaf(w.z, o.z, acc2[i]);
            acc2[i] = fmaf(w.w, o.w, acc2[i]);
        }
    }
#pragma unroll 2
    for (int k4 = 0; k4 < 32; k4++) {
        float4 w = Wf4[vc * 64 + 32 + k4];
#pragma unroll
        for (int i = 0; i < 16; i++) {
            float4 cx = cs4[(2 * i + sg) * 32 + k4];
            acc2[i] = fmaf(w.x, cx.x, acc2[i]);
            acc2[i] = fmaf(w.y, cx.y, acc2[i]);
            acc2[i] = fmaf(w.z, cx.z, acc2[i]);
            acc2[i] = fmaf(w.w, cx.w, acc2[i]);
        }
    }
#pragma unroll
    for (int i = 0; i < 16; i++)
        logits[((size_t)b * Sn + s0 + 2 * i + sg) * Vv + vc] = acc2[i] + bb;
}

// ============================================================================
// launch
// ============================================================================
extern "C" void kernel_launch(void* const* d_in, const int* in_sizes, int n_in,
                              void* d_out, int out_size) {
    const int*   x   = (const int*)d_in[0];
    const float* emb = (const float*)d_in[1];
    const float* Wih = (const float*)d_in[2];
    const float* Whh = (const float*)d_in[3];
    const float* bih = (const float*)d_in[4];
    const float* bhh = (const float*)d_in[5];
    const float* Wq  = (const float*)d_in[6];
    const float* bq  = (const float*)d_in[7];
    const float* Wk  = (const float*)d_in[8];
    const float* bk  = (const float*)d_in[9];
    const float* v   = (const float*)d_in[10];
    const float* Wf  = (const float*)d_in[11];
    const float* bf  = (const float*)d_in[12];

    float* out    = (float*)d_out;
    float* logits = out;

    const int LOGITS_N = Bn * Sn * Vv;
    float* hT;
    float* cT;
    if (out_size >= LOGITS_N + 2 * Bn * Hd) {
        hT = out + LOGITS_N;
        cT = hT + Bn * Hd;
    } else {
        float* dump = nullptr;
        cudaGetSymbolAddress((void**)&dump, g_state_dump);
        hT = dump;
        cT = dump + Bn * Hd;
    }

    k_embed_xproj<<<128, 512>>>(x, emb, Wih, bih, bhh);
    k_lstm<<<CL * Bn, 256>>>(Whh, hT, cT);      // 4 clusters of 4 CTAs
    k_qk<<<128, 256>>>(Wq, bq, Wk, bk);
    k_scores<<<544, 256>>>(v);
    k_ctx_logits<<<64, 256>>>(Wf, bf, logits);
}

// round 17
// speedup vs baseline: 1.0418x; 1.0418x over previous
#include <cuda_runtime.h>
#include <math.h>
#include <stdint.h>

#define Bn 4
#define Sn 512
#define Hd 128
#define En 32     // embed_dim — E=32 (V,E,H = 128,32,128)
#define Vv 128
#define G4 512    // 4*H
#define CL 4      // cluster size for LSTM

typedef unsigned long long u64;

// ---------------- scratch (device globals: no allocation allowed) ----------------
__device__ float g_xproj[Bn*Sn*G4];   // 4 MB
__device__ float g_out[Bn*Sn*Hd];     // 1 MB
__device__ float g_q[Bn*Sn*Hd];       // 1 MB
__device__ float g_k[Bn*Sn*Hd];       // 1 MB
__device__ float g_scores[Bn*Sn*Sn];  // 4 MB (raw scores; softmax fused downstream)
__device__ float g_state_dump[2*Bn*Hd];

// ---------------- helpers ----------------
__device__ __forceinline__ u64 fma2(u64 a, u64 b, u64 c) {
    u64 d;
    asm("fma.rn.f32x2 %0, %1, %2, %3;" : "=l"(d) : "l"(a), "l"(b), "l"(c));
    return d;
}
__device__ __forceinline__ u64 add2(u64 a, u64 b) {
    u64 d;
    asm("add.rn.f32x2 %0, %1, %2;" : "=l"(d) : "l"(a), "l"(b));
    return d;
}
__device__ __forceinline__ float sig_f(float x) {
    return __fdividef(1.0f, 1.0f + __expf(-x));
}
__device__ __forceinline__ float tanh_f(float x) {
    float e = __expf(-2.0f * x);
    return __fdividef(1.0f - e, 1.0f + e);
}
__device__ __forceinline__ float tanh_a(float x) {
    float y;
    asm("tanh.approx.f32 %0, %1;" : "=f"(y) : "f"(x));
    return y;
}
__device__ __forceinline__ uint32_t smem_u32(const void* p) {
    uint32_t a;
    asm("{ .reg .u64 t; cvta.to.shared.u64 t, %1; cvt.u32.u64 %0, t; }"
        : "=r"(a) : "l"(p));
    return a;
}
__device__ __forceinline__ uint32_t mapa_peer(uint32_t local_addr, uint32_t peer_rank) {
    uint32_t r;
    asm("mapa.shared::cluster.u32 %0, %1, %2;" : "=r"(r) : "r"(local_addr), "r"(peer_rank));
    return r;
}
__device__ __forceinline__ void mbar_init(uint32_t mbar, uint32_t count) {
    asm volatile("mbarrier.init.shared.b64 [%0], %1;" :: "r"(mbar), "r"(count) : "memory");
}
__device__ __forceinline__ void mbar_expect_tx(uint32_t mbar, uint32_t bytes) {
    asm volatile("mbarrier.arrive.expect_tx.shared.b64 _, [%0], %1;"
                 :: "r"(mbar), "r"(bytes) : "memory");
}
__device__ __forceinline__ void st_async_b32(uint32_t dst, float v, uint32_t mbar) {
    asm volatile(
        "st.async.shared::cluster.mbarrier::complete_tx::bytes.b32 [%0], %1, [%2];"
        :: "r"(dst), "r"(__float_as_uint(v)), "r"(mbar) : "memory");
}
__device__ __forceinline__ void mbar_wait_cta(uint32_t mbar, uint32_t parity) {
    uint32_t done;
    asm volatile(
        "{\n\t"
        ".reg .pred p;\n\t"
        "mbarrier.try_wait.parity.acquire.cta.shared::cta.b64 p, [%1], %2;\n\t"
        "selp.b32 %0, 1, 0, p;\n\t"
        "}"
        : "=r"(done) : "r"(mbar), "r"(parity) : "memory");
    if (!done) {
        asm volatile(
            "{\n\t"
            ".reg .pred P;\n\t"
            "WAIT_LOOP_%=:\n\t"
            "mbarrier.try_wait.parity.acquire.cta.shared::cta.b64 P, [%0], %1, 0x989680;\n\t"
            "@P bra.uni WAIT_DONE_%=;\n\t"
            "bra.uni WAIT_LOOP_%=;\n\t"
            "WAIT_DONE_%=:\n\t"
            "}"
            :: "r"(mbar), "r"(parity) : "memory");
    }
}

// ============================================================================
// Kernel 1: xproj[r, col] = dot(emb[x[r], :32], W_ih[col, :32]) + b_ih + b_hh
// ============================================================================
__global__ void k_embed_xproj(const int* __restrict__ x, const float* __restrict__ emb,
                              const float* __restrict__ Wih, const float* __restrict__ bih,
                              const float* __restrict__ bhh) {
    __shared__ __align__(16) float e_s[16 * En];
    int tid = threadIdx.x;                          // 512
    int r0 = blockIdx.x * 16;
    e_s[tid] = emb[x[r0 + (tid >> 5)] * En + (tid & 31)];
    __syncthreads();

    int col = tid;
    const float4* W4 = (const float4*)(Wih + col * En);
    float4 w[8];
#pragma unroll
    for (int i = 0; i < 8; i++) w[i] = W4[i];
    float bb = bih[col] + bhh[col];

#pragma unroll 4
    for (int r = 0; r < 16; r++) {
        const float4* e4 = (const float4*)(e_s + r * En);
        float a = bb;
#pragma unroll
        for (int i = 0; i < 8; i++) {
            float4 e = e4[i];
            a = fmaf(w[i].x, e.x, a);
            a = fmaf(w[i].y, e.y, a);
            a = fmaf(w[i].z, e.z, a);
            a = fmaf(w[i].w, e.w, a);
        }
        g_xproj[(size_t)(r0 + r) * G4 + col] = a;
    }
}

// ============================================================================
// Kernel 2: LSTM — r15 version (proven 432us). 4-CTA cluster per batch,
// gate-partitioned rows, all weights in registers, activated-gate st.async
// exchange with split stores (p==0 ships {local, rank+1}; p==1 ships
// {rank+2, rank+3}), consumers-only wait, double-banked dots.
// ============================================================================
__global__ void __cluster_dims__(CL, 1, 1) __launch_bounds__(256, 1)
k_lstm(const float* __restrict__ Whh, float* __restrict__ hT, float* __restrict__ cT) {
    __shared__ __align__(16) float h_s[128];
    __shared__ __align__(16) float dots[2][512];
    __shared__ __align__(8)  u64  mbar[2];

    int tid = threadIdx.x;
    uint32_t rank;
    asm("mov.u32 %0, %%cluster_ctarank;" : "=r"(rank));
    int b = blockIdx.x / CL;
    int row_local  = tid >> 1;
    int p          = tid & 1;
    int row_global = (int)rank * 128 + row_local;
    bool is_g_gate = (rank == 2);                      // CTA-uniform activation

    // 64 weight floats (half row) -> 32 u64 register pairs
    const ulonglong2* wsrc = (const ulonglong2*)(Whh + (size_t)row_global * Hd + p * 64);
    u64 w[32];
#pragma unroll
    for (int q = 0; q < 16; q++) {
        ulonglong2 v = wsrc[q];
        w[2 * q]     = v.x;
        w[2 * q + 1] = v.y;
    }

    uint32_t mbar_a[2] = { smem_u32(&mbar[0]), smem_u32(&mbar[1]) };
    uint32_t dloc[2]   = { smem_u32(&dots[0][row_global]), smem_u32(&dots[1][row_global]) };
    uint32_t dr[3][2], mr[3][2];
#pragma unroll
    for (int i = 0; i < 3; i++) {
        uint32_t pr = (rank + 1 + i) & 3;
        dr[i][0] = mapa_peer(dloc[0], pr);
        dr[i][1] = mapa_peer(dloc[1], pr);
        mr[i][0] = mapa_peer(mbar_a[0], pr);
        mr[i][1] = mapa_peer(mbar_a[1], pr);
    }

    if (tid < 128) h_s[tid] = 0.0f;
    if (tid == 0) {
        mbar_init(mbar_a[0], 1);   // 1 arrival per phase (tid0's arrive.expect_tx)
        mbar_init(mbar_a[1], 1);
    }
    float c = 0.0f, hlast = 0.0f, clast = 0.0f;

    // cluster barrier: mbarrier init + h_s visible before any remote traffic
    asm volatile("barrier.cluster.arrive.aligned;" ::: "memory");
    asm volatile("barrier.cluster.wait.aligned;" ::: "memory");

    const ulonglong2* h2v = (const ulonglong2*)h_s;   // 32 groups of 4 floats
    const float* xpb  = g_xproj + (size_t)b * Sn * G4;
    float*       outb = g_out   + (size_t)b * Sn * Hd;
    int hq = p * 16;                                   // this half's h range

    // software-pipelined xproj: xprow holds step t's value at loop top
    float xprow = xpb[row_global];                     // t = 0

    for (int t = 0; t < Sn; t++) {
        uint32_t bank = t & 1;
        uint32_t par  = (t >> 1) & 1;
        // arm this step's barrier: 512 gate stores x 4B = 2048B total
        if (tid == 0)
            mbar_expect_tx(mbar_a[bank], 2048);
        // prefetch step t+1's xproj NOW — consumed a full iteration later
        float xprow_next = (t + 1 < Sn) ? xpb[(size_t)(t + 1) * G4 + row_global] : 0.0f;

        // phase A: half-row dot (64 MACs = 32 fma2), h via LDS.128 broadcast
        u64 a0 = 0ull, a1 = 0ull, a2 = 0ull, a3 = 0ull;
#pragma unroll
        for (int q = 0; q < 16; q += 2) {
            ulonglong2 hv0 = h2v[hq + q];
            ulonglong2 hv1 = h2v[hq + q + 1];
            a0 = fma2(w[2 * q],     hv0.x, a0);
            a1 = fma2(w[2 * q + 1], hv0.y, a1);
            a2 = fma2(w[2 * q + 2], hv1.x, a2);
            a3 = fma2(w[2 * q + 3], hv1.y, a3);
        }
        u64 ssum = add2(add2(a0, a1), add2(a2, a3));
        float2 sf = *(float2*)&ssum;
        float mysum = sf.x + sf.y;
        mysum += __shfl_xor_sync(0xFFFFFFFFu, mysum, 1);
        // BOTH lanes hold the full dot -> identical activation; split the 4 copies.
        float pre = xprow + mysum;
        float act = is_g_gate ? tanh_f(pre) : sig_f(pre);
        if (p == 0) {
            st_async_b32(dloc[bank],  act, mbar_a[bank]);   // local
            st_async_b32(dr[0][bank], act, mr[0][bank]);    // rank+1
        } else {
            st_async_b32(dr[1][bank], act, mr[1][bank]);    // rank+2
            st_async_b32(dr[2][bank], act, mr[2][bank]);    // rank+3
        }

        // only phase-B consumers wait (warps 0-3)
        if (tid < 128) {
            mbar_wait_cta(mbar_a[bank], par);
            const float* ds = dots[bank];
            float ai = ds[tid];
            float af = ds[tid + 128];
            float ag = ds[tid + 256];
            float ao = ds[tid + 384];
            c = af * c + ai * ag;
            float h = ao * tanh_f(c);
            h_s[tid] = h;
            if (rank == 0) {
                outb[(size_t)t * Hd + tid] = h;
                hlast = h;
                clast = c;
            }
        }
        // orders h_s writes before every thread's next phase-A reads;
        // transitively bounds cross-CTA skew to one step.
        __syncthreads();
        xprow = xprow_next;
    }
    if (rank == 0 && tid < 128) {
        hT[b * Hd + tid] = hlast;
        cT[b * Hd + tid] = clast;
    }
    // no CTA may exit while peer remote ops could be in flight
    asm volatile("barrier.cluster.arrive.aligned;" ::: "memory");
    asm volatile("barrier.cluster.wait.aligned;" ::: "memory");
}

// ============================================================================
// Kernel 3: q = out @ Wqᵀ + bq ; k = out @ Wkᵀ + bk. 16 rows/block, 256 thr.
// ============================================================================
__global__ void k_qk(const float* __restrict__ Wq, const float* __restrict__ bq,
                     const float* __restrict__ Wk, const float* __restrict__ bk) {
    __shared__ __align__(16) float o_s[16 * 128];
    int tid = threadIdx.x;
    int r0 = blockIdx.x * 16;
    for (int i = tid; i < 2048; i += 256)
        o_s[i] = g_out[(size_t)r0 * Hd + i];
    __syncthreads();

    const float* W    = (tid < 128) ? Wq : Wk;
    const float* bias = (tid < 128) ? bq : bk;
    float*       dst  = (tid < 128) ? g_q : g_k;
    int c = tid & 127;

    const float4* W4  = (const float4*)W;
    const float4* os4 = (const float4*)o_s;
    float acc[16];
    float bb = bias[c];
#pragma unroll
    for (int r = 0; r < 16; r++) acc[r] = bb;
#pragma unroll 4
    for (int k4 = 0; k4 < 32; k4++) {
        float4 w = W4[c * 32 + k4];
#pragma unroll
        for (int r = 0; r < 16; r++) {
            float4 o = os4[r * 32 + k4];
            acc[r] = fmaf(w.x, o.x, acc[r]);
            acc[r] = fmaf(w.y, o.y, acc[r]);
            acc[r] = fmaf(w.z, o.z, acc[r]);
            acc[r] = fmaf(w.w, o.w, acc[r]);
        }
    }
#pragma unroll
    for (int r = 0; r < 16; r++)
        dst[(size_t)(r0 + r) * Hd + c] = acc[r];
}

// ============================================================================
// Kernel 4: RAW scores via tanh.approx. 16x32 causal tiles (2x the blocks of
// the 32x32 version -> fixes grid-size-bound occupancy: 544 -> 1088 CTAs).
// Per batch: s-band si (16 rows) x t-tile ti (32 cols), ti <= si/2 -> 272 tiles.
// ============================================================================
__global__ void k_scores(const float* __restrict__ v) {
    __shared__ __align__(16) float q_s[16 * 128];
    __shared__ float kT[128 * 33];
    __shared__ float v_s[128];
    int tid = threadIdx.x;
    int b = blockIdx.x / 272;
    int r = blockIdx.x % 272;
    // find s-band: counts(si) = si/2 + 1, cumulative search
    int si = 0, base = 0;
    while (base + (si >> 1) + 1 <= r) {
        base += (si >> 1) + 1;
        si++;
    }
    int ti = r - base;
    int s0 = si * 16, t0 = ti * 32;

    const float* qb = g_q + ((size_t)b * Sn + s0) * Hd;
    const float* kb = g_k + ((size_t)b * Sn + t0) * Hd;
    for (int i = tid; i < 2048; i += 256) q_s[i] = qb[i];
    for (int i = tid; i < 4096; i += 256) {
        int tt = i >> 7, h = i & 127;
        kT[h * 33 + tt] = kb[i];
    }
    if (tid < 128) v_s[tid] = v[tid];
    __syncthreads();

    int tl = tid & 31, sb = tid >> 5;     // sb in 0..7; rows sb and sb+8
    float acc0 = 0.f, acc1 = 0.f;
#pragma unroll 2
    for (int h = 0; h < 128; h++) {
        float kv = kT[h * 33 + tl];
        float vv = v_s[h];
        acc0 = fmaf(vv, tanh_a(q_s[sb * 128 + h] + kv), acc0);
        acc1 = fmaf(vv, tanh_a(q_s[(sb + 8) * 128 + h] + kv), acc1);
    }
    int t = t0 + tl;
    int s_a = s0 + sb;
    int s_b = s0 + sb + 8;
    if (t <= s_a)
        g_scores[((size_t)b * Sn + s_a) * Sn + t] = acc0;
    if (t <= s_b)
        g_scores[((size_t)b * Sn + s_b) * Sn + t] = acc1;
}

// ============================================================================
// Kernel 5: FUSED softmax + ctx + logits. 32 s-rows/block, 256 threads.
// ============================================================================
__global__ void k_ctx_logits(const float* __restrict__ Wf, const float* __restrict__ bf,
                             float* __restrict__ logits) {
    __shared__ float w_s[32 * 32];
    __shared__ __align__(16) float ctx_s[32 * 128];
    __shared__ __align__(16) float out_s[32 * 128];
    __shared__ float m_s[32], iz_s[32];
    int tid = threadIdx.x;
    int b  = blockIdx.x >> 4;
    int s0 = (blockIdx.x & 15) << 5;

    for (int i = tid; i < 4096; i += 256)
        out_s[i] = g_out[((size_t)b * Sn + s0) * Hd + i];

    // ---- pass 1: softmax stats (8 lanes per row) ----
    {
        int row = tid >> 3;
        int l8  = tid & 7;
        int s = s0 + row;
        int n = s + 1;
        const float* sc = g_scores + ((size_t)b * Sn + s) * Sn;
        float mx = -1e30f;
        for (int t = l8; t < n; t += 8)
            mx = fmaxf(mx, sc[t]);
#pragma unroll
        for (int o = 4; o > 0; o >>= 1)
            mx = fmaxf(mx, __shfl_xor_sync(0xFFFFFFFFu, mx, o));
        float sum = 0.0f;
        for (int t = l8; t < n; t += 8)
            sum += __expf(sc[t] - mx);
#pragma unroll
        for (int o = 4; o > 0; o >>= 1)
            sum += __shfl_xor_sync(0xFFFFFFFFu, sum, o);
        if (l8 == 0) {
            m_s[row]  = mx;
            iz_s[row] = __fdividef(1.0f, sum);
        }
    }
    __syncthreads();

    // ---- pass 2: ctx = softmax(scores) @ out ----
    int h = tid & 127, sg = tid >> 7;
    float acc[16];
#pragma unroll
    for (int i = 0; i < 16; i++) acc[i] = 0.0f;

    int tend = s0 + 32;
    for (int tc0 = 0; tc0 < tend; tc0 += 32) {
        __syncthreads();
        for (int i = tid; i < 1024; i += 256) {
            int sl = i >> 5, tc = i & 31;
            int s = s0 + sl;
            int t = tc0 + tc;
            float wv = 0.0f;
            if (t <= s)
                wv = __expf(g_scores[((size_t)b * Sn + s) * Sn + t] - m_s[sl]) * iz_s[sl];
            w_s[i] = wv;
        }
        __syncthreads();
#pragma unroll 4
        for (int tc = 0; tc < 32; tc++) {
            float ov = g_out[((size_t)b * Sn + tc0 + tc) * Hd + h];
#pragma unroll
            for (int i = 0; i < 16; i++)
                acc[i] = fmaf(w_s[(2 * i + sg) * 32 + tc], ov, acc[i]);
        }
    }
    __syncthreads();
#pragma unroll
    for (int i = 0; i < 16; i++) ctx_s[(2 * i + sg) * 128 + h] = acc[i];
    __syncthreads();

    // ---- logits tile ----
    int vc = tid & 127;
    float bb = bf[vc];
    const float4* Wf4 = (const float4*)Wf;
    const float4* os4 = (const float4*)out_s;
    const float4* cs4 = (const float4*)ctx_s;
    float acc2[16];
#pragma unroll
    for (int i = 0; i < 16; i++) acc2[i] = 0.0f;
#pragma unroll 2
    for (int k4 = 0; k4 < 32; k4++) {
        float4 w = Wf4[vc * 64 + k4];
#pragma unroll
        for (int i = 0; i < 16; i++) {
            float4 o = os4[(2 * i + sg) * 32 + k4];
            acc2[i] = fmaf(w.x, o.x, acc2[i]);
            acc2[i] = fmaf(w.y, o.y, acc2[i]);
            acc2[i] = fmaf(w.z, o.z, acc2[i]);
            acc2[i] = fmaf(w.w, o.w, acc2[i]);
        }
    }
#pragma unroll 2
    for (int k4 = 0; k4 < 32; k4++) {
        float4 w = Wf4[vc * 64 + 32 + k4];
#pragma unroll
        for (int i = 0; i < 16; i++) {
            float4 cx = cs4[(2 * i + sg) * 32 + k4];
            acc2[i] = fmaf(w.x, cx.x, acc2[i]);
            acc2[i] = fmaf(w.y, cx.y, acc2[i]);
            acc2[i] = fmaf(w.z, cx.z, acc2[i]);
            acc2[i] = fmaf(w.w, cx.w, acc2[i]);
        }
    }
#pragma unroll
    for (int i = 0; i < 16; i++)
        logits[((size_t)b * Sn + s0 + 2 * i + sg) * Vv + vc] = acc2[i] + bb;
}

// ============================================================================
// launch
// ============================================================================
extern "C" void kernel_launch(void* const* d_in, const int* in_sizes, int n_in,
                              void* d_out, int out_size) {
    const int*   x   = (const int*)d_in[0];
    const float* emb = (const float*)d_in[1];
    const float* Wih = (const float*)d_in[2];
    const float* Whh = (const float*)d_in[3];
    const float* bih = (const float*)d_in[4];
    const float* bhh = (const float*)d_in[5];
    const float* Wq  = (const float*)d_in[6];
    const float* bq  = (const float*)d_in[7];
    const float* Wk  = (const float*)d_in[8];
    const float* bk  = (const float*)d_in[9];
    const float* v   = (const float*)d_in[10];
    const float* Wf  = (const float*)d_in[11];
    const float* bf  = (const float*)d_in[12];

    float* out    = (float*)d_out;
    float* logits = out;

    const int LOGITS_N = Bn * Sn * Vv;
    float* hT;
    float* cT;
    if (out_size >= LOGITS_N + 2 * Bn * Hd) {
        hT = out + LOGITS_N;
        cT = hT + Bn * Hd;
    } else {
        float* dump = nullptr;
        cudaGetSymbolAddress((void**)&dump, g_state_dump);
        hT = dump;
        cT = dump + Bn * Hd;
    }

    k_embed_xproj<<<128, 512>>>(x, emb, Wih, bih, bhh);
    k_lstm<<<CL * Bn, 256>>>(Whh, hT, cT);      // 4 clusters of 4 CTAs
    k_qk<<<128, 256>>>(Wq, bq, Wk, bk);
    k_scores<<<Bn * 272, 256>>>(v);
    k_ctx_logits<<<64, 256>>>(Wf, bf, logits);
}